// round 9
// baseline (speedup 1.0000x reference)
#include <cuda_runtime.h>
#include <math.h>
#include <stdint.h>

// ---------------- problem constants ----------------
#define BB 4
#define TT 1024
#define CC 768
#define HH 12
#define HD 64
#define MM (BB*TT)          // 4096 rows
#define C3 (3*CC)           // 2304
#define C4 (4*CC)           // 3072

// ---------------- scratch (device globals; no allocation) ----------------
__device__ float g_h[MM*CC];
__device__ float g_qkv[MM*C3];
__device__ float g_att[MM*CC];
__device__ float g_x1[MM*CC];
__device__ float g_fc[MM*C4];
__device__ float g_tbl[TT*HD];

// ================= rpe table =================
__global__ void build_table_kernel(float* __restrict__ tbl) {
    int d = blockIdx.x;      // distance 0..1023
    int c = threadIdx.x;     // 0..63
    int k = (c < 32) ? c : (c - 32);
    double invf = pow(10000.0, -((double)(2 * k)) / 64.0);
    double ang = (double)d * invf;
    double v = (c < 32) ? sin(ang) : cos(ang);
    tbl[d * HD + c] = (float)v;
}

// ================= layernorm =================
__global__ void ln_kernel(const float* __restrict__ x, const float* __restrict__ w,
                          float* __restrict__ out) {
    int row = blockIdx.x;
    int tid = threadIdx.x;
    const float* xr = x + (size_t)row * CC;
    float v0 = xr[tid], v1 = xr[tid + 256], v2 = xr[tid + 512];
    float s  = v0 + v1 + v2;
    float sq = v0*v0 + v1*v1 + v2*v2;
    #pragma unroll
    for (int off = 16; off >= 1; off >>= 1) {
        s  += __shfl_xor_sync(0xffffffffu, s,  off);
        sq += __shfl_xor_sync(0xffffffffu, sq, off);
    }
    __shared__ float ps[8], psq[8];
    int warp = tid >> 5, lane = tid & 31;
    if (lane == 0) { ps[warp] = s; psq[warp] = sq; }
    __syncthreads();
    float S = 0.f, SQ = 0.f;
    #pragma unroll
    for (int i = 0; i < 8; i++) { S += ps[i]; SQ += psq[i]; }
    float mean = S * (1.0f / CC);
    float var  = SQ * (1.0f / CC) - mean * mean;
    float rstd = rsqrtf(var + 1e-5f);
    float* orow = out + (size_t)row * CC;
    orow[tid      ] = (v0 - mean) * rstd * w[tid      ];
    orow[tid + 256] = (v1 - mean) * rstd * w[tid + 256];
    orow[tid + 512] = (v2 - mean) * rstd * w[tid + 512];
}

// ========== tf32 tensor-core GEMM: 128x128x16 tile, 256 thr, mma.m16n8k8 ==========
// C = A[M,K] @ B[K,N] row-major. EPI: 0 plain, 1 exact GELU, 2 add residual.
__device__ __forceinline__ float gelu_exact(float v) {
    return 0.5f * v * (1.0f + erff(v * 0.70710678118654752f));
}
__device__ __forceinline__ float to_tf32(float f) {
    uint32_t u;
    asm("cvt.rna.tf32.f32 %0, %1;" : "=r"(u) : "f"(f));
    return __uint_as_float(u);
}
__device__ __forceinline__ void mma_tf32(float c[4],
    uint32_t a0, uint32_t a1, uint32_t a2, uint32_t a3,
    uint32_t b0, uint32_t b1) {
    asm volatile(
        "mma.sync.aligned.m16n8k8.row.col.f32.tf32.tf32.f32 "
        "{%0,%1,%2,%3}, {%4,%5,%6,%7}, {%8,%9}, {%0,%1,%2,%3};"
        : "+f"(c[0]), "+f"(c[1]), "+f"(c[2]), "+f"(c[3])
        : "r"(a0), "r"(a1), "r"(a2), "r"(a3), "r"(b0), "r"(b1));
}

template <int EPI>
__global__ __launch_bounds__(256, 2) void gemm_tf32_kernel(
    const float* __restrict__ A, const float* __restrict__ B,
    float* __restrict__ Cp, const float* __restrict__ res,
    int M, int N, int K) {
    __shared__ float As[2][128][20];    // [m][k], pad 20 -> frag loads conflict-free
    __shared__ float Bs[2][16][136];    // [k][n], pad 136 -> conflict-free

    int tid = threadIdx.x;
    int m0 = blockIdx.y * 128, n0 = blockIdx.x * 128;
    int lane = tid & 31, g = lane >> 2, t = lane & 3;
    int warpId = tid >> 5;
    int wm = warpId >> 2, wn = warpId & 3;       // 2 x 4 warp grid
    int mW = wm * 64, nW = wn * 32;              // 64x32 per warp

    float acc[4][4][4];
    #pragma unroll
    for (int i = 0; i < 4; i++)
        #pragma unroll
        for (int j = 0; j < 4; j++)
            #pragma unroll
            for (int r = 0; r < 4; r++) acc[i][j][r] = 0.f;

    int ar = tid >> 2;              // 0..63
    int ac = (tid & 3) * 4;         // 0,4,8,12
    const float* Aptr0 = A + (size_t)(m0 + ar) * K + ac;
    const float* Aptr1 = Aptr0 + (size_t)64 * K;
    int br = tid >> 5;              // 0..7
    int bc = (tid & 31) * 4;        // 0..124
    const float* Bptr0 = B + (size_t)br * N + n0 + bc;
    const float* Bptr1 = Bptr0 + (size_t)8 * N;

    // ---- preload tile 0 (convert to tf32 at store) ----
    {
        float4 a0v = *(const float4*)(Aptr0);
        float4 a1v = *(const float4*)(Aptr1);
        float4 b0v = *(const float4*)(Bptr0);
        float4 b1v = *(const float4*)(Bptr1);
        float4 sa0 = make_float4(to_tf32(a0v.x), to_tf32(a0v.y), to_tf32(a0v.z), to_tf32(a0v.w));
        float4 sa1 = make_float4(to_tf32(a1v.x), to_tf32(a1v.y), to_tf32(a1v.z), to_tf32(a1v.w));
        float4 sb0 = make_float4(to_tf32(b0v.x), to_tf32(b0v.y), to_tf32(b0v.z), to_tf32(b0v.w));
        float4 sb1 = make_float4(to_tf32(b1v.x), to_tf32(b1v.y), to_tf32(b1v.z), to_tf32(b1v.w));
        *(float4*)&As[0][ar     ][ac] = sa0;
        *(float4*)&As[0][ar + 64][ac] = sa1;
        *(float4*)&Bs[0][br     ][bc] = sb0;
        *(float4*)&Bs[0][br + 8 ][bc] = sb1;
    }
    __syncthreads();

    int cur = 0;
    for (int k0 = 16; k0 <= K; k0 += 16) {
        float4 a0n, a1n, b0n, b1n;
        bool more = (k0 < K);
        if (more) {   // global prefetch overlapped with mma on current buffer
            a0n = *(const float4*)(Aptr0 + k0);
            a1n = *(const float4*)(Aptr1 + k0);
            b0n = *(const float4*)(Bptr0 + (size_t)k0 * N);
            b1n = *(const float4*)(Bptr1 + (size_t)k0 * N);
        }
        // ---- compute on current buffer: two k-steps of 8 ----
        #pragma unroll
        for (int kk = 0; kk < 16; kk += 8) {
            uint32_t afr[4][4], bfr[4][2];
            #pragma unroll
            for (int mt = 0; mt < 4; mt++) {
                int r0 = mW + mt * 16 + g;
                afr[mt][0] = __float_as_uint(As[cur][r0    ][kk + t    ]);
                afr[mt][1] = __float_as_uint(As[cur][r0 + 8][kk + t    ]);
                afr[mt][2] = __float_as_uint(As[cur][r0    ][kk + t + 4]);
                afr[mt][3] = __float_as_uint(As[cur][r0 + 8][kk + t + 4]);
            }
            #pragma unroll
            for (int nt = 0; nt < 4; nt++) {
                int cN = nW + nt * 8 + g;
                bfr[nt][0] = __float_as_uint(Bs[cur][kk + t    ][cN]);
                bfr[nt][1] = __float_as_uint(Bs[cur][kk + t + 4][cN]);
            }
            #pragma unroll
            for (int mt = 0; mt < 4; mt++)
                #pragma unroll
                for (int nt = 0; nt < 4; nt++)
                    mma_tf32(acc[mt][nt],
                             afr[mt][0], afr[mt][1], afr[mt][2], afr[mt][3],
                             bfr[nt][0], bfr[nt][1]);
        }
        if (more) {
            int nxt = cur ^ 1;
            float4 sa0 = make_float4(to_tf32(a0n.x), to_tf32(a0n.y), to_tf32(a0n.z), to_tf32(a0n.w));
            float4 sa1 = make_float4(to_tf32(a1n.x), to_tf32(a1n.y), to_tf32(a1n.z), to_tf32(a1n.w));
            float4 sb0 = make_float4(to_tf32(b0n.x), to_tf32(b0n.y), to_tf32(b0n.z), to_tf32(b0n.w));
            float4 sb1 = make_float4(to_tf32(b1n.x), to_tf32(b1n.y), to_tf32(b1n.z), to_tf32(b1n.w));
            *(float4*)&As[nxt][ar     ][ac] = sa0;
            *(float4*)&As[nxt][ar + 64][ac] = sa1;
            *(float4*)&Bs[nxt][br     ][bc] = sb0;
            *(float4*)&Bs[nxt][br + 8 ][bc] = sb1;
            __syncthreads();
            cur = nxt;
        }
    }

    // ---- epilogue: c0,c1 at (g, 2t), c2,c3 at (g+8, 2t) ----
    #pragma unroll
    for (int mt = 0; mt < 4; mt++) {
        #pragma unroll
        for (int nt = 0; nt < 4; nt++) {
            int r0 = m0 + mW + mt * 16 + g;
            int c  = n0 + nW + nt * 8 + 2 * t;
            #pragma unroll
            for (int half = 0; half < 2; half++) {
                int r = r0 + half * 8;
                size_t idx = (size_t)r * N + c;
                float2 v;
                v.x = acc[mt][nt][half * 2 + 0];
                v.y = acc[mt][nt][half * 2 + 1];
                if (EPI == 1) {
                    v.x = gelu_exact(v.x); v.y = gelu_exact(v.y);
                } else if (EPI == 2) {
                    float2 rr = *(const float2*)(res + idx);
                    v.x += rr.x; v.y += rr.y;
                }
                *(float2*)(Cp + idx) = v;
            }
        }
    }
}

// ================= fused flash attention with relative-position bias ===========
#define P65 65
__global__ __launch_bounds__(256) void attn_kernel(
    const float* __restrict__ qkv, const float* __restrict__ tbl,
    float* __restrict__ out) {
    extern __shared__ float smf[];
    float* Qs = smf;                      // [64][65]
    float* Ks = smf + 64 * P65;           // [64][65] aliased with PsT[j][i]
    float* Vs = smf + 2 * 64 * P65;       // [64][65]
    float* Ts = smf + 3 * 64 * P65;       // [127][65]

    int tid = threadIdx.x;
    int tx = tid & 15, ty = tid >> 4;
    int i0 = blockIdx.x * 64;
    int h  = blockIdx.y;
    int b  = blockIdx.z;
    const float scale = 0.125f;

    for (int it = tid; it < 64 * 16; it += 256) {
        int r = it >> 4, c4 = (it & 15) * 4;
        float4 v = *(const float4*)(qkv + ((size_t)(b * TT + i0 + r)) * C3 + h * HD + c4);
        Qs[r * P65 + c4 + 0] = v.x * scale;
        Qs[r * P65 + c4 + 1] = v.y * scale;
        Qs[r * P65 + c4 + 2] = v.z * scale;
        Qs[r * P65 + c4 + 3] = v.w * scale;
    }

    float m_i[4], l_i[4], acc_o[4][4];
    #pragma unroll
    for (int ii = 0; ii < 4; ii++) {
        m_i[ii] = -INFINITY; l_i[ii] = 0.f;
        #pragma unroll
        for (int jj = 0; jj < 4; jj++) acc_o[ii][jj] = 0.f;
    }
    int base = ty * 4 - tx * 4 + 63;

    for (int j0 = 0; j0 <= i0; j0 += 64) {
        __syncthreads();
        for (int it = tid; it < 64 * 16; it += 256) {
            int r = it >> 4, c4 = (it & 15) * 4;
            size_t rowoff = ((size_t)(b * TT + j0 + r)) * C3 + h * HD + c4;
            float4 kv = *(const float4*)(qkv + rowoff + CC);
            float4 vv = *(const float4*)(qkv + rowoff + 2 * CC);
            Ks[r * P65 + c4 + 0] = kv.x; Ks[r * P65 + c4 + 1] = kv.y;
            Ks[r * P65 + c4 + 2] = kv.z; Ks[r * P65 + c4 + 3] = kv.w;
            Vs[r * P65 + c4 + 0] = vv.x; Vs[r * P65 + c4 + 1] = vv.y;
            Vs[r * P65 + c4 + 2] = vv.z; Vs[r * P65 + c4 + 3] = vv.w;
        }
        for (int it = tid; it < 127 * 16; it += 256) {
            int rr = it >> 4, c4 = (it & 15) * 4;
            int dd = i0 - j0 - 63 + rr;
            float4 v;
            if (dd >= 0) v = *(const float4*)(tbl + (size_t)dd * HD + c4);
            else { v.x = v.y = v.z = v.w = 0.f; }
            Ts[rr * P65 + c4 + 0] = v.x; Ts[rr * P65 + c4 + 1] = v.y;
            Ts[rr * P65 + c4 + 2] = v.z; Ts[rr * P65 + c4 + 3] = v.w;
        }
        __syncthreads();

        float acc[4][4];
        #pragma unroll
        for (int ii = 0; ii < 4; ii++)
            #pragma unroll
            for (int jj = 0; jj < 4; jj++) acc[ii][jj] = 0.f;

        #pragma unroll 2
        for (int d = 0; d < 64; d++) {
            float q[4], k[4], t[7];
            #pragma unroll
            for (int ii = 0; ii < 4; ii++) q[ii] = Qs[(ty * 4 + ii) * P65 + d];
            #pragma unroll
            for (int jj = 0; jj < 4; jj++) k[jj] = Ks[(tx * 4 + jj) * P65 + d];
            #pragma unroll
            for (int o = 0; o < 7; o++)   t[o]  = Ts[(base - 3 + o) * P65 + d];
            #pragma unroll
            for (int ii = 0; ii < 4; ii++)
                #pragma unroll
                for (int jj = 0; jj < 4; jj++) {
                    acc[ii][jj] += q[ii] * k[jj];
                    acc[ii][jj] += q[ii] * t[3 + ii - jj];
                }
        }
        if (j0 == i0) {
            #pragma unroll
            for (int ii = 0; ii < 4; ii++)
                #pragma unroll
                for (int jj = 0; jj < 4; jj++)
                    if (ty * 4 + ii < tx * 4 + jj) acc[ii][jj] = -INFINITY;
        }

        float mloc[4];
        #pragma unroll
        for (int ii = 0; ii < 4; ii++) {
            mloc[ii] = fmaxf(fmaxf(acc[ii][0], acc[ii][1]),
                             fmaxf(acc[ii][2], acc[ii][3]));
            #pragma unroll
            for (int off = 8; off >= 1; off >>= 1)
                mloc[ii] = fmaxf(mloc[ii], __shfl_xor_sync(0xffffffffu, mloc[ii], off, 16));
        }
        float p[4][4], psum[4], alpha[4];
        #pragma unroll
        for (int ii = 0; ii < 4; ii++) {
            float m_new = fmaxf(m_i[ii], mloc[ii]);
            alpha[ii] = __expf(m_i[ii] - m_new);      // args <= 0; -inf -> 0
            psum[ii] = 0.f;
            #pragma unroll
            for (int jj = 0; jj < 4; jj++) {
                p[ii][jj] = __expf(acc[ii][jj] - m_new);  // masked -> 0
                psum[ii] += p[ii][jj];
            }
            m_i[ii] = m_new;
        }
        #pragma unroll
        for (int ii = 0; ii < 4; ii++) {
            #pragma unroll
            for (int off = 8; off >= 1; off >>= 1)
                psum[ii] += __shfl_xor_sync(0xffffffffu, psum[ii], off, 16);
            l_i[ii] = l_i[ii] * alpha[ii] + psum[ii];
            #pragma unroll
            for (int jj = 0; jj < 4; jj++) acc_o[ii][jj] *= alpha[ii];
        }

        __syncthreads();
        #pragma unroll
        for (int ii = 0; ii < 4; ii++)
            #pragma unroll
            for (int jj = 0; jj < 4; jj++)
                Ks[(tx * 4 + jj) * P65 + ty * 4 + ii] = p[ii][jj];
        __syncthreads();

        #pragma unroll 4
        for (int j = 0; j < 64; j++) {
            float pv[4], vv[4];
            #pragma unroll
            for (int ii = 0; ii < 4; ii++) pv[ii] = Ks[j * P65 + ty * 4 + ii];
            #pragma unroll
            for (int jj = 0; jj < 4; jj++) vv[jj] = Vs[j * P65 + tx * 4 + jj];
            #pragma unroll
            for (int ii = 0; ii < 4; ii++)
                #pragma unroll
                for (int jj = 0; jj < 4; jj++)
                    acc_o[ii][jj] += pv[ii] * vv[jj];
        }
    }

    #pragma unroll
    for (int ii = 0; ii < 4; ii++) {
        float inv_l = 1.0f / l_i[ii];
        float4 o;
        o.x = acc_o[ii][0] * inv_l; o.y = acc_o[ii][1] * inv_l;
        o.z = acc_o[ii][2] * inv_l; o.w = acc_o[ii][3] * inv_l;
        size_t idx = ((size_t)(b * TT + i0 + ty * 4 + ii)) * CC + h * HD + tx * 4;
        *(float4*)(out + idx) = o;
    }
}

// ================= launch =================
extern "C" void kernel_launch(void* const* d_in, const int* in_sizes, int n_in,
                              void* d_out, int out_size) {
    const float* x       = (const float*)d_in[0];
    const float* ln1_w   = (const float*)d_in[1];
    const float* w_attn  = (const float*)d_in[2];
    // d_in[3] = w_pos: dead code in reference, unused
    const float* w_cproj = (const float*)d_in[4];
    const float* ln2_w   = (const float*)d_in[5];
    const float* w_fc    = (const float*)d_in[6];
    const float* w_mproj = (const float*)d_in[7];
    float* out = (float*)d_out;

    float *p_h, *p_qkv, *p_att, *p_x1, *p_fc, *p_tbl;
    cudaGetSymbolAddress((void**)&p_h,   g_h);
    cudaGetSymbolAddress((void**)&p_qkv, g_qkv);
    cudaGetSymbolAddress((void**)&p_att, g_att);
    cudaGetSymbolAddress((void**)&p_x1,  g_x1);
    cudaGetSymbolAddress((void**)&p_fc,  g_fc);
    cudaGetSymbolAddress((void**)&p_tbl, g_tbl);

    static const size_t ATTN_SMEM = (3 * 64 * P65 + 127 * P65) * sizeof(float);
    cudaFuncSetAttribute(attn_kernel, cudaFuncAttributeMaxDynamicSharedMemorySize,
                         (int)ATTN_SMEM);

    // 1. rpe table
    build_table_kernel<<<TT, HD>>>(p_tbl);
    // 2. LN1
    ln_kernel<<<MM, 256>>>(x, ln1_w, p_h);
    // 3. qkv = h @ w_attn
    gemm_tf32_kernel<0><<<dim3(C3 / 128, MM / 128), 256>>>(p_h, w_attn, p_qkv, nullptr, MM, C3, CC);
    // 4. attention (flash + rpe bias)
    attn_kernel<<<dim3(TT / 64, HH, BB), 256, ATTN_SMEM>>>(p_qkv, p_tbl, p_att);
    // 5. x1 = x + att @ w_cproj
    gemm_tf32_kernel<2><<<dim3(CC / 128, MM / 128), 256>>>(p_att, w_cproj, p_x1, x, MM, CC, CC);
    // 6. LN2
    ln_kernel<<<MM, 256>>>(p_x1, ln2_w, p_h);
    // 7. fc = gelu(h @ w_fc)
    gemm_tf32_kernel<1><<<dim3(C4 / 128, MM / 128), 256>>>(p_h, w_fc, p_fc, nullptr, MM, C4, CC);
    // 8. out = x1 + fc @ w_mproj
    gemm_tf32_kernel<2><<<dim3(CC / 128, MM / 128), 256>>>(p_fc, w_mproj, out, p_x1, MM, CC, C4);
}

// round 11
// speedup vs baseline: 1.5047x; 1.5047x over previous
#include <cuda_runtime.h>
#include <math.h>
#include <stdint.h>

// ---------------- problem constants ----------------
#define BB 4
#define TT 1024
#define CC 768
#define HH 12
#define HD 64
#define MM (BB*TT)          // 4096 rows
#define C3 (3*CC)           // 2304
#define C4 (4*CC)           // 3072

// ---------------- scratch (device globals; no allocation) ----------------
__device__ float g_h[MM*CC];
__device__ float g_qkv[MM*C3];
__device__ float g_att[MM*CC];
__device__ float g_x1[MM*CC];
__device__ float g_fc[MM*C4];
__device__ float g_tbl[TT*HD];

// ================= rpe table =================
__global__ void build_table_kernel(float* __restrict__ tbl) {
    int d = blockIdx.x;      // distance 0..1023
    int c = threadIdx.x;     // 0..63
    int k = (c < 32) ? c : (c - 32);
    double invf = pow(10000.0, -((double)(2 * k)) / 64.0);
    double ang = (double)d * invf;
    double v = (c < 32) ? sin(ang) : cos(ang);
    tbl[d * HD + c] = (float)v;
}

// ================= layernorm =================
__global__ void ln_kernel(const float* __restrict__ x, const float* __restrict__ w,
                          float* __restrict__ out) {
    int row = blockIdx.x;
    int tid = threadIdx.x;
    const float* xr = x + (size_t)row * CC;
    float v0 = xr[tid], v1 = xr[tid + 256], v2 = xr[tid + 512];
    float s  = v0 + v1 + v2;
    float sq = v0*v0 + v1*v1 + v2*v2;
    #pragma unroll
    for (int off = 16; off >= 1; off >>= 1) {
        s  += __shfl_xor_sync(0xffffffffu, s,  off);
        sq += __shfl_xor_sync(0xffffffffu, sq, off);
    }
    __shared__ float ps[8], psq[8];
    int warp = tid >> 5, lane = tid & 31;
    if (lane == 0) { ps[warp] = s; psq[warp] = sq; }
    __syncthreads();
    float S = 0.f, SQ = 0.f;
    #pragma unroll
    for (int i = 0; i < 8; i++) { S += ps[i]; SQ += psq[i]; }
    float mean = S * (1.0f / CC);
    float var  = SQ * (1.0f / CC) - mean * mean;
    float rstd = rsqrtf(var + 1e-5f);
    float* orow = out + (size_t)row * CC;
    orow[tid      ] = (v0 - mean) * rstd * w[tid      ];
    orow[tid + 256] = (v1 - mean) * rstd * w[tid + 256];
    orow[tid + 512] = (v2 - mean) * rstd * w[tid + 512];
}

// ================= shared mma helpers =================
__device__ __forceinline__ float gelu_exact(float v) {
    return 0.5f * v * (1.0f + erff(v * 0.70710678118654752f));
}
__device__ __forceinline__ float to_tf32(float f) {
    uint32_t u;
    asm("cvt.rna.tf32.f32 %0, %1;" : "=r"(u) : "f"(f));
    return __uint_as_float(u);
}
__device__ __forceinline__ void mma_tf32(float c[4],
    uint32_t a0, uint32_t a1, uint32_t a2, uint32_t a3,
    uint32_t b0, uint32_t b1) {
    asm volatile(
        "mma.sync.aligned.m16n8k8.row.col.f32.tf32.tf32.f32 "
        "{%0,%1,%2,%3}, {%4,%5,%6,%7}, {%8,%9}, {%0,%1,%2,%3};"
        : "+f"(c[0]), "+f"(c[1]), "+f"(c[2]), "+f"(c[3])
        : "r"(a0), "r"(a1), "r"(a2), "r"(a3), "r"(b0), "r"(b1));
}

// ========== tf32 tensor-core GEMM: 128x128x16 tile, 256 thr, mma.m16n8k8 ==========
template <int EPI>
__global__ __launch_bounds__(256, 2) void gemm_tf32_kernel(
    const float* __restrict__ A, const float* __restrict__ B,
    float* __restrict__ Cp, const float* __restrict__ res,
    int M, int N, int K) {
    __shared__ float As[2][128][20];
    __shared__ float Bs[2][16][136];

    int tid = threadIdx.x;
    int m0 = blockIdx.y * 128, n0 = blockIdx.x * 128;
    int lane = tid & 31, g = lane >> 2, t = lane & 3;
    int warpId = tid >> 5;
    int wm = warpId >> 2, wn = warpId & 3;
    int mW = wm * 64, nW = wn * 32;

    float acc[4][4][4];
    #pragma unroll
    for (int i = 0; i < 4; i++)
        #pragma unroll
        for (int j = 0; j < 4; j++)
            #pragma unroll
            for (int r = 0; r < 4; r++) acc[i][j][r] = 0.f;

    int ar = tid >> 2;
    int ac = (tid & 3) * 4;
    const float* Aptr0 = A + (size_t)(m0 + ar) * K + ac;
    const float* Aptr1 = Aptr0 + (size_t)64 * K;
    int br = tid >> 5;
    int bc = (tid & 31) * 4;
    const float* Bptr0 = B + (size_t)br * N + n0 + bc;
    const float* Bptr1 = Bptr0 + (size_t)8 * N;

    {
        float4 a0v = *(const float4*)(Aptr0);
        float4 a1v = *(const float4*)(Aptr1);
        float4 b0v = *(const float4*)(Bptr0);
        float4 b1v = *(const float4*)(Bptr1);
        float4 sa0 = make_float4(to_tf32(a0v.x), to_tf32(a0v.y), to_tf32(a0v.z), to_tf32(a0v.w));
        float4 sa1 = make_float4(to_tf32(a1v.x), to_tf32(a1v.y), to_tf32(a1v.z), to_tf32(a1v.w));
        float4 sb0 = make_float4(to_tf32(b0v.x), to_tf32(b0v.y), to_tf32(b0v.z), to_tf32(b0v.w));
        float4 sb1 = make_float4(to_tf32(b1v.x), to_tf32(b1v.y), to_tf32(b1v.z), to_tf32(b1v.w));
        *(float4*)&As[0][ar     ][ac] = sa0;
        *(float4*)&As[0][ar + 64][ac] = sa1;
        *(float4*)&Bs[0][br     ][bc] = sb0;
        *(float4*)&Bs[0][br + 8 ][bc] = sb1;
    }
    __syncthreads();

    int cur = 0;
    for (int k0 = 16; k0 <= K; k0 += 16) {
        float4 a0n, a1n, b0n, b1n;
        bool more = (k0 < K);
        if (more) {
            a0n = *(const float4*)(Aptr0 + k0);
            a1n = *(const float4*)(Aptr1 + k0);
            b0n = *(const float4*)(Bptr0 + (size_t)k0 * N);
            b1n = *(const float4*)(Bptr1 + (size_t)k0 * N);
        }
        #pragma unroll
        for (int kk = 0; kk < 16; kk += 8) {
            uint32_t afr[4][4], bfr[4][2];
            #pragma unroll
            for (int mt = 0; mt < 4; mt++) {
                int r0 = mW + mt * 16 + g;
                afr[mt][0] = __float_as_uint(As[cur][r0    ][kk + t    ]);
                afr[mt][1] = __float_as_uint(As[cur][r0 + 8][kk + t    ]);
                afr[mt][2] = __float_as_uint(As[cur][r0    ][kk + t + 4]);
                afr[mt][3] = __float_as_uint(As[cur][r0 + 8][kk + t + 4]);
            }
            #pragma unroll
            for (int nt = 0; nt < 4; nt++) {
                int cN = nW + nt * 8 + g;
                bfr[nt][0] = __float_as_uint(Bs[cur][kk + t    ][cN]);
                bfr[nt][1] = __float_as_uint(Bs[cur][kk + t + 4][cN]);
            }
            #pragma unroll
            for (int mt = 0; mt < 4; mt++)
                #pragma unroll
                for (int nt = 0; nt < 4; nt++)
                    mma_tf32(acc[mt][nt],
                             afr[mt][0], afr[mt][1], afr[mt][2], afr[mt][3],
                             bfr[nt][0], bfr[nt][1]);
        }
        if (more) {
            int nxt = cur ^ 1;
            float4 sa0 = make_float4(to_tf32(a0n.x), to_tf32(a0n.y), to_tf32(a0n.z), to_tf32(a0n.w));
            float4 sa1 = make_float4(to_tf32(a1n.x), to_tf32(a1n.y), to_tf32(a1n.z), to_tf32(a1n.w));
            float4 sb0 = make_float4(to_tf32(b0n.x), to_tf32(b0n.y), to_tf32(b0n.z), to_tf32(b0n.w));
            float4 sb1 = make_float4(to_tf32(b1n.x), to_tf32(b1n.y), to_tf32(b1n.z), to_tf32(b1n.w));
            *(float4*)&As[nxt][ar     ][ac] = sa0;
            *(float4*)&As[nxt][ar + 64][ac] = sa1;
            *(float4*)&Bs[nxt][br     ][bc] = sb0;
            *(float4*)&Bs[nxt][br + 8 ][bc] = sb1;
            __syncthreads();
            cur = nxt;
        }
    }

    #pragma unroll
    for (int mt = 0; mt < 4; mt++) {
        #pragma unroll
        for (int nt = 0; nt < 4; nt++) {
            int r0 = m0 + mW + mt * 16 + g;
            int c  = n0 + nW + nt * 8 + 2 * t;
            #pragma unroll
            for (int half = 0; half < 2; half++) {
                int r = r0 + half * 8;
                size_t idx = (size_t)r * N + c;
                float2 v;
                v.x = acc[mt][nt][half * 2 + 0];
                v.y = acc[mt][nt][half * 2 + 1];
                if (EPI == 1) {
                    v.x = gelu_exact(v.x); v.y = gelu_exact(v.y);
                } else if (EPI == 2) {
                    float2 rr = *(const float2*)(res + idx);
                    v.x += rr.x; v.y += rr.y;
                }
                *(float2*)(Cp + idx) = v;
            }
        }
    }
}

// ================ tensor-core flash attention with RPE bias ====================
// Block: 128 Q-rows x (loop over 64-col KV tiles). 256 threads = 8 warps,
// warp w owns rows [16w,16w+16). S = Q@K^T (mma), bias via R = Q@Ts^T (mma) +
// per-element smem gather (Toeplitz), online softmax in fragments, PV via mma.
#define AP 68          // pitch: Q/K/VT/Ts/Ps  ((4g+t)%32 bijective -> conflict-free frags)
#define RP 84          // pitch: R band buffer
#define SM_Q  0
#define SM_K  8704     // 128*68
#define SM_VT 13056    // +64*68
#define SM_T  17408    // +64*68
#define SM_R  30464    // +192*68
#define SM_P  41216    // +128*84
#define SM_TOT 49920   // +128*68  (floats) = 199,680 B

__global__ __launch_bounds__(256, 1) void attn_mma_kernel(
    const float* __restrict__ qkv, const float* __restrict__ tbl,
    float* __restrict__ out) {
    extern __shared__ float sm[];
    float* Qs = sm + SM_Q;     // [128][AP]  pre-scaled Q
    float* Ks = sm + SM_K;     // [64][AP]   K[j][d]
    float* VT = sm + SM_VT;    // [64][AP]   V^T[d][j]
    float* Ts = sm + SM_T;     // [192][AP]  table rows rr=0..191 (191 zero-padded)
    float* Rs = sm + SM_R;     // [128][RP]  per-warp R band (local cols)
    float* Ps = sm + SM_P;     // [128][AP]  softmaxed P

    int tid = threadIdx.x;
    int lane = tid & 31, w = tid >> 5;
    int g = lane >> 2, t = lane & 3;
    int ib = (int)gridDim.x - 1 - (int)blockIdx.x;   // heavy blocks first
    int i0 = ib * 128;
    int h = blockIdx.y, b = blockIdx.z;
    int m0w = w * 16;

    // load Q tile (pre-scaled by 1/sqrt(HD))
    for (int it = tid; it < 128 * 16; it += 256) {
        int r = it >> 4, c4 = (it & 15) * 4;
        float4 v = *(const float4*)(qkv + ((size_t)(b * TT + i0 + r)) * C3 + h * HD + c4);
        Qs[r * AP + c4 + 0] = v.x * 0.125f;
        Qs[r * AP + c4 + 1] = v.y * 0.125f;
        Qs[r * AP + c4 + 2] = v.z * 0.125f;
        Qs[r * AP + c4 + 3] = v.w * 0.125f;
    }

    float m_i[2] = {-INFINITY, -INFINITY};
    float l_i[2] = {0.f, 0.f};
    float accO[8][4];
    #pragma unroll
    for (int nt = 0; nt < 8; nt++)
        #pragma unroll
        for (int r = 0; r < 4; r++) accO[nt][r] = 0.f;

    int njt = 2 * ib + 2;      // tiles j0 = 0..i0+64
    for (int jt = 0; jt < njt; jt++) {
        int j0 = jt * 64;
        __syncthreads();   // prev iter readers of Ks/VT/Ts/Ps done
        // K tile [j][d]
        for (int it = tid; it < 64 * 16; it += 256) {
            int r = it >> 4, c4 = (it & 15) * 4;
            float4 kv = *(const float4*)(qkv + ((size_t)(b * TT + j0 + r)) * C3 + CC + h * HD + c4);
            Ks[r * AP + c4 + 0] = kv.x; Ks[r * AP + c4 + 1] = kv.y;
            Ks[r * AP + c4 + 2] = kv.z; Ks[r * AP + c4 + 3] = kv.w;
        }
        // V^T tile [d][j]: lanes vary j -> conflict-free STS
        {
            int j = tid & 63, dq = tid >> 6;     // dq 0..3
            #pragma unroll
            for (int ch = 0; ch < 4; ch++) {
                int d4 = dq * 16 + ch * 4;
                float4 vv = *(const float4*)(qkv + ((size_t)(b * TT + j0 + j)) * C3 + 2 * CC + h * HD + d4);
                VT[(d4 + 0) * AP + j] = vv.x; VT[(d4 + 1) * AP + j] = vv.y;
                VT[(d4 + 2) * AP + j] = vv.z; VT[(d4 + 3) * AP + j] = vv.w;
            }
        }
        // table rows: rr = i_loc - j_loc + 63 in [0,191]; dd = i0-j0-63+rr
        // (rr=191 only feeds an R column that is never gathered; zero-fill keeps it defined
        //  and the dd<TT clamp prevents OOB when i0-j0+128 > 1023)
        for (int it = tid; it < 192 * 16; it += 256) {
            int rr = it >> 4, c4 = (it & 15) * 4;
            int dd = i0 - j0 - 63 + rr;
            float4 v;
            if (dd >= 0 && dd < TT) v = *(const float4*)(tbl + (size_t)dd * HD + c4);
            else { v.x = v.y = v.z = v.w = 0.f; }
            Ts[rr * AP + c4 + 0] = v.x; Ts[rr * AP + c4 + 1] = v.y;
            Ts[rr * AP + c4 + 2] = v.z; Ts[rr * AP + c4 + 3] = v.w;
        }
        __syncthreads();

        // ---- score + R mmas ----
        float accS[8][4], accR[10][4];
        #pragma unroll
        for (int nt = 0; nt < 8; nt++)
            #pragma unroll
            for (int r = 0; r < 4; r++) accS[nt][r] = 0.f;
        #pragma unroll
        for (int rt = 0; rt < 10; rt++)
            #pragma unroll
            for (int r = 0; r < 4; r++) accR[rt][r] = 0.f;

        #pragma unroll
        for (int ks = 0; ks < 8; ks++) {
            int kk = ks * 8;
            uint32_t a0 = __float_as_uint(Qs[(m0w + g    ) * AP + kk + t    ]);
            uint32_t a1 = __float_as_uint(Qs[(m0w + g + 8) * AP + kk + t    ]);
            uint32_t a2 = __float_as_uint(Qs[(m0w + g    ) * AP + kk + t + 4]);
            uint32_t a3 = __float_as_uint(Qs[(m0w + g + 8) * AP + kk + t + 4]);
            #pragma unroll
            for (int nt = 0; nt < 8; nt++) {
                uint32_t b0 = __float_as_uint(Ks[(nt * 8 + g) * AP + kk + t    ]);
                uint32_t b1 = __float_as_uint(Ks[(nt * 8 + g) * AP + kk + t + 4]);
                mma_tf32(accS[nt], a0, a1, a2, a3, b0, b1);
            }
            #pragma unroll
            for (int rt = 0; rt < 10; rt++) {
                int cT = m0w + rt * 8 + g;       // warp band: rr in [16w,16w+79]
                uint32_t b0 = __float_as_uint(Ts[cT * AP + kk + t    ]);
                uint32_t b1 = __float_as_uint(Ts[cT * AP + kk + t + 4]);
                mma_tf32(accR[rt], a0, a1, a2, a3, b0, b1);
            }
        }

        // ---- stash R band (local cols = rr - 16w), own rows only ----
        #pragma unroll
        for (int rt = 0; rt < 10; rt++) {
            *(float2*)&Rs[(m0w + g    ) * RP + rt * 8 + 2 * t] = make_float2(accR[rt][0], accR[rt][1]);
            *(float2*)&Rs[(m0w + g + 8) * RP + rt * 8 + 2 * t] = make_float2(accR[rt][2], accR[rt][3]);
        }
        __syncwarp();

        // ---- gather bias + causal mask ----
        #pragma unroll
        for (int nt = 0; nt < 8; nt++) {
            #pragma unroll
            for (int r = 0; r < 4; r++) {
                int il = m0w + g + ((r & 2) ? 8 : 0);
                int jl = nt * 8 + 2 * t + (r & 1);
                if (i0 + il < j0 + jl) accS[nt][r] = -INFINITY;
                else accS[nt][r] += Rs[il * RP + (il - jl + 63 - m0w)];
            }
        }

        // ---- online softmax (rows m0w+g and m0w+g+8; quad lanes share a row) ----
        float mloc[2] = {-INFINITY, -INFINITY};
        #pragma unroll
        for (int nt = 0; nt < 8; nt++) {
            mloc[0] = fmaxf(mloc[0], fmaxf(accS[nt][0], accS[nt][1]));
            mloc[1] = fmaxf(mloc[1], fmaxf(accS[nt][2], accS[nt][3]));
        }
        #pragma unroll
        for (int hh = 0; hh < 2; hh++) {
            mloc[hh] = fmaxf(mloc[hh], __shfl_xor_sync(0xffffffffu, mloc[hh], 1));
            mloc[hh] = fmaxf(mloc[hh], __shfl_xor_sync(0xffffffffu, mloc[hh], 2));
        }
        float mnew[2] = {fmaxf(m_i[0], mloc[0]), fmaxf(m_i[1], mloc[1])};
        float alpha[2] = {__expf(m_i[0] - mnew[0]), __expf(m_i[1] - mnew[1])};
        float psum[2] = {0.f, 0.f};
        #pragma unroll
        for (int nt = 0; nt < 8; nt++) {
            #pragma unroll
            for (int r = 0; r < 4; r++) {
                float p = __expf(accS[nt][r] - mnew[r >> 1]);   // -inf -> 0
                accS[nt][r] = p;
                psum[r >> 1] += p;
            }
        }
        #pragma unroll
        for (int hh = 0; hh < 2; hh++) {
            psum[hh] += __shfl_xor_sync(0xffffffffu, psum[hh], 1);
            psum[hh] += __shfl_xor_sync(0xffffffffu, psum[hh], 2);
            l_i[hh] = l_i[hh] * alpha[hh] + psum[hh];
            m_i[hh] = mnew[hh];
        }
        #pragma unroll
        for (int nt = 0; nt < 8; nt++) {
            accO[nt][0] *= alpha[0]; accO[nt][1] *= alpha[0];
            accO[nt][2] *= alpha[1]; accO[nt][3] *= alpha[1];
        }

        // ---- P to smem (own rows), then PV mma ----
        #pragma unroll
        for (int nt = 0; nt < 8; nt++) {
            *(float2*)&Ps[(m0w + g    ) * AP + nt * 8 + 2 * t] = make_float2(accS[nt][0], accS[nt][1]);
            *(float2*)&Ps[(m0w + g + 8) * AP + nt * 8 + 2 * t] = make_float2(accS[nt][2], accS[nt][3]);
        }
        __syncwarp();

        #pragma unroll
        for (int ks = 0; ks < 8; ks++) {
            int kk = ks * 8;
            uint32_t a0 = __float_as_uint(Ps[(m0w + g    ) * AP + kk + t    ]);
            uint32_t a1 = __float_as_uint(Ps[(m0w + g + 8) * AP + kk + t    ]);
            uint32_t a2 = __float_as_uint(Ps[(m0w + g    ) * AP + kk + t + 4]);
            uint32_t a3 = __float_as_uint(Ps[(m0w + g + 8) * AP + kk + t + 4]);
            #pragma unroll
            for (int nt = 0; nt < 8; nt++) {
                uint32_t b0 = __float_as_uint(VT[(nt * 8 + g) * AP + kk + t    ]);
                uint32_t b1 = __float_as_uint(VT[(nt * 8 + g) * AP + kk + t + 4]);
                mma_tf32(accO[nt], a0, a1, a2, a3, b0, b1);
            }
        }
    }

    // ---- epilogue: out[B,T,C] ----
    float inv0 = 1.0f / l_i[0], inv1 = 1.0f / l_i[1];
    #pragma unroll
    for (int nt = 0; nt < 8; nt++) {
        int c = h * HD + nt * 8 + 2 * t;
        size_t i0r = (size_t)(b * TT + i0 + m0w + g) * CC + c;
        *(float2*)(out + i0r)            = make_float2(accO[nt][0] * inv0, accO[nt][1] * inv0);
        *(float2*)(out + i0r + 8 * CC)   = make_float2(accO[nt][2] * inv1, accO[nt][3] * inv1);
    }
}

// ================= launch =================
extern "C" void kernel_launch(void* const* d_in, const int* in_sizes, int n_in,
                              void* d_out, int out_size) {
    const float* x       = (const float*)d_in[0];
    const float* ln1_w   = (const float*)d_in[1];
    const float* w_attn  = (const float*)d_in[2];
    // d_in[3] = w_pos: dead code in reference, unused
    const float* w_cproj = (const float*)d_in[4];
    const float* ln2_w   = (const float*)d_in[5];
    const float* w_fc    = (const float*)d_in[6];
    const float* w_mproj = (const float*)d_in[7];
    float* out = (float*)d_out;

    float *p_h, *p_qkv, *p_att, *p_x1, *p_fc, *p_tbl;
    cudaGetSymbolAddress((void**)&p_h,   g_h);
    cudaGetSymbolAddress((void**)&p_qkv, g_qkv);
    cudaGetSymbolAddress((void**)&p_att, g_att);
    cudaGetSymbolAddress((void**)&p_x1,  g_x1);
    cudaGetSymbolAddress((void**)&p_fc,  g_fc);
    cudaGetSymbolAddress((void**)&p_tbl, g_tbl);

    static const size_t ATTN_SMEM = SM_TOT * sizeof(float);   // 199,680 B
    cudaFuncSetAttribute(attn_mma_kernel, cudaFuncAttributeMaxDynamicSharedMemorySize,
                         (int)ATTN_SMEM);

    // 1. rpe table
    build_table_kernel<<<TT, HD>>>(p_tbl);
    // 2. LN1
    ln_kernel<<<MM, 256>>>(x, ln1_w, p_h);
    // 3. qkv = h @ w_attn
    gemm_tf32_kernel<0><<<dim3(C3 / 128, MM / 128), 256>>>(p_h, w_attn, p_qkv, nullptr, MM, C3, CC);
    // 4. attention (tensor-core flash + rpe bias)
    attn_mma_kernel<<<dim3(TT / 128, HH, BB), 256, ATTN_SMEM>>>(p_qkv, p_tbl, p_att);
    // 5. x1 = x + att @ w_cproj
    gemm_tf32_kernel<2><<<dim3(CC / 128, MM / 128), 256>>>(p_att, w_cproj, p_x1, x, MM, CC, CC);
    // 6. LN2
    ln_kernel<<<MM, 256>>>(p_x1, ln2_w, p_h);
    // 7. fc = gelu(h @ w_fc)
    gemm_tf32_kernel<1><<<dim3(C4 / 128, MM / 128), 256>>>(p_h, w_fc, p_fc, nullptr, MM, C4, CC);
    // 8. out = x1 + fc @ w_mproj
    gemm_tf32_kernel<2><<<dim3(CC / 128, MM / 128), 256>>>(p_fc, w_mproj, out, p_x1, MM, CC, C4);
}